// round 13
// baseline (speedup 1.0000x reference)
#include <cuda_runtime.h>
#include <cstdint>

// EdgeUpdate via mma.sync.m16n8k8.tf32, 512 threads / 16 warps (R7 structure).
// Single delta vs R7(848us): GEMM2 pair-packed (k,k+4) via shfl -> LDS.64 loads.
#define THREADS 512
#define NTILES  5000          // 640000 / 128
#define PXS     132           // uint2 row stride (132 mod 16 = 4 -> conflict-free)

// smem byte offsets
#define OW1 0                 // uint2 [128 pr][128 n]  : 131072 B
#define OW2 131072            // uint2 [ 64 pr][128 n]  :  65536 B
#define OX  196608            // pair buffer [32 pr][132] uint2 = 33792 B / red
#define SMEM_BYTES (196608 + 34816)   // 231424

__device__ __forceinline__ unsigned tf32r(float x) {
  unsigned r; asm("cvt.rna.tf32.f32 %0, %1;" : "=r"(r) : "f"(x)); return r;
}
__device__ __forceinline__ float silu_f(float x) {
  return x * (1.0f / (1.0f + __expf(-x)));
}
__device__ __forceinline__ void mma8(float* d, unsigned a0, unsigned a1,
                                     unsigned a2, unsigned a3,
                                     unsigned b0, unsigned b1) {
  asm volatile("mma.sync.aligned.m16n8k8.row.col.f32.tf32.tf32.f32 "
    "{%0,%1,%2,%3}, {%4,%5,%6,%7}, {%8,%9}, {%0,%1,%2,%3};"
    : "+f"(d[0]), "+f"(d[1]), "+f"(d[2]), "+f"(d[3])
    : "r"(a0), "r"(a1), "r"(a2), "r"(a3), "r"(b0), "r"(b1));
}

__global__ void __launch_bounds__(THREADS, 1)
edge_update_mma7(const float* __restrict__ nodes,
                 const float* __restrict__ efeat,
                 const int*   __restrict__ srcI,
                 const int*   __restrict__ dstI,
                 const float* __restrict__ W1,
                 const float* __restrict__ b1,
                 const float* __restrict__ W2,
                 const float* __restrict__ b2,
                 const float* __restrict__ gamma,
                 const float* __restrict__ beta,
                 float* __restrict__ out)
{
  extern __shared__ char smem[];
  uint2* w1p = (uint2*)(smem + OW1);
  uint2* w2p = (uint2*)(smem + OW2);
  uint2* pxu = (uint2*)(smem + OX);   // [32 pr][PXS] pairs (x chunks AND h1)

  const int tid  = threadIdx.x;
  const int warp = tid >> 5, lane = tid & 31;
  const int kl = lane & 3, r = lane >> 2;
  const int mi = warp >> 2;            // edges [32*mi, 32*mi+32)
  const int nj = warp & 3;             // outs  [32*nj, 32*nj+32)
  const int mbase = mi * 32;
  const int nbase = nj * 32;

  // ---- stage weights as (k, k+4) tf32 pairs, swizzled n ^ ((pr&3)<<2) ----
  for (int i = tid; i < 16384; i += THREADS) {
    int pr = i >> 7, n = i & 127;
    int k0 = (pr >> 2) * 8 + (pr & 3);
    w1p[pr * 128 + (n ^ ((pr & 3) << 2))] =
        make_uint2(tf32r(W1[k0 * 128 + n]), tf32r(W1[(k0 + 4) * 128 + n]));
  }
  for (int i = tid; i < 8192; i += THREADS) {
    int pr = i >> 7, n = i & 127;
    int k0 = (pr >> 2) * 8 + (pr & 3);
    w2p[pr * 128 + (n ^ ((pr & 3) << 2))] =
        make_uint2(tf32r(W2[k0 * 128 + n]), tf32r(W2[(k0 + 4) * 128 + n]));
  }
  // persistent per-lane bias/affine (R7-proven)
  float b1v[4][2], b2v[4][2], gv[4][2], btv[4][2];
#pragma unroll
  for (int u = 0; u < 4; u++) {
    int n = nbase + u * 8 + 2 * kl;
    b1v[u][0] = b1[n];    b1v[u][1] = b1[n + 1];
    b2v[u][0] = b2[n];    b2v[u][1] = b2[n + 1];
    gv[u][0]  = gamma[n]; gv[u][1]  = gamma[n + 1];
    btv[u][0] = beta[n];  btv[u][1] = beta[n + 1];
  }
  __syncthreads();

  for (int tile = blockIdx.x; tile < NTILES; tile += gridDim.x) {
    const int e0 = tile * 128;

    // ================= GEMM1: D1 = X[128,256] @ W1 (R7 verbatim) ===========
    float d1[2][4][4];
#pragma unroll
    for (int t = 0; t < 2; t++)
#pragma unroll
      for (int u = 0; u < 4; u++)
#pragma unroll
        for (int j = 0; j < 4; j++) d1[t][u][j] = 0.f;

#pragma unroll 1
    for (int c = 0; c < 4; c++) {
      __syncthreads();   // previous pxu use complete
      {
        const int e = tid & 127, q4 = tid >> 7;
        const float* base;
        if (c == 0)      base = nodes + (size_t)srcI[e0 + e] * 64;
        else if (c == 1) base = nodes + (size_t)dstI[e0 + e] * 64;
        else             base = efeat + (size_t)(e0 + e) * 128 + (c - 2) * 64;
#pragma unroll
        for (int gg = 0; gg < 2; gg++) {
          int g = q4 * 2 + gg;
          float4 v0 = ((const float4*)(base + g * 8))[0];
          float4 v1 = ((const float4*)(base + g * 8))[1];
          pxu[(4 * g + 0) * PXS + e] = make_uint2(__float_as_uint(v0.x), __float_as_uint(v1.x));
          pxu[(4 * g + 1) * PXS + e] = make_uint2(__float_as_uint(v0.y), __float_as_uint(v1.y));
          pxu[(4 * g + 2) * PXS + e] = make_uint2(__float_as_uint(v0.z), __float_as_uint(v1.z));
          pxu[(4 * g + 3) * PXS + e] = make_uint2(__float_as_uint(v0.w), __float_as_uint(v1.w));
        }
      }
      __syncthreads();

      const int prc = c * 32;
#pragma unroll
      for (int k8 = 0; k8 < 8; k8++) {
        const int prb = k8 * 4 + kl;
        uint2 a0[2], a1[2], bb[4];
#pragma unroll
        for (int t = 0; t < 2; t++) {
          int m = mbase + t * 16 + r;
          a0[t] = pxu[prb * PXS + m];
          a1[t] = pxu[prb * PXS + m + 8];
        }
#pragma unroll
        for (int u = 0; u < 4; u++) {
          int n = nbase + u * 8 + r;
          bb[u] = w1p[(prc + prb) * 128 + (n ^ (kl << 2))];
        }
#pragma unroll
        for (int t = 0; t < 2; t++)
#pragma unroll
          for (int u = 0; u < 4; u++)
            mma8(d1[t][u], a0[t].x, a1[t].x, a0[t].y, a1[t].y, bb[u].x, bb[u].y);
      }
    }

    // ---- h1 = silu(D1 + b1), raw fp32 bits ----
    unsigned h1f[2][4][4];
#pragma unroll
    for (int t = 0; t < 2; t++)
#pragma unroll
      for (int u = 0; u < 4; u++) {
        h1f[t][u][0] = __float_as_uint(silu_f(d1[t][u][0] + b1v[u][0]));
        h1f[t][u][1] = __float_as_uint(silu_f(d1[t][u][1] + b1v[u][1]));
        h1f[t][u][2] = __float_as_uint(silu_f(d1[t][u][2] + b1v[u][0]));
        h1f[t][u][3] = __float_as_uint(silu_f(d1[t][u][3] + b1v[u][1]));
      }

    // ================= GEMM2: D2 = H1[128,128] @ W2, pair-packed ===========
    float d2[2][4][4];
#pragma unroll
    for (int t = 0; t < 2; t++)
#pragma unroll
      for (int u = 0; u < 4; u++)
#pragma unroll
        for (int j = 0; j < 4; j++) d2[t][u][j] = 0.f;

#pragma unroll 1
    for (int c2 = 0; c2 < 2; c2++) {
      __syncthreads();   // prior pxu reads done
      // warps whose n-band is this round's k-range store h1 as (k,k+4) pairs
      if ((nj >> 1) == c2) {
#pragma unroll
        for (int t = 0; t < 2; t++)
#pragma unroll
          for (int u = 0; u < 4; u++) {
            unsigned p0 = __shfl_xor_sync(0xffffffffu, h1f[t][u][0], 2);
            unsigned p1 = __shfl_xor_sync(0xffffffffu, h1f[t][u][1], 2);
            unsigned p2 = __shfl_xor_sync(0xffffffffu, h1f[t][u][2], 2);
            unsigned p3 = __shfl_xor_sync(0xffffffffu, h1f[t][u][3], 2);
            if (kl < 2) {
              int ka = (nj & 1) * 32 + u * 8 + 2 * kl;   // local k in [0,64)
              int pra = (ka >> 3) * 4 + (ka & 3);        // pair row
              int m = mbase + t * 16 + r;
              pxu[pra * PXS + m]           = make_uint2(h1f[t][u][0], p0);
              pxu[pra * PXS + m + 8]       = make_uint2(h1f[t][u][2], p2);
              pxu[(pra + 1) * PXS + m]     = make_uint2(h1f[t][u][1], p1);
              pxu[(pra + 1) * PXS + m + 8] = make_uint2(h1f[t][u][3], p3);
            }
          }
      }
      __syncthreads();

      const int prc = c2 * 32;
#pragma unroll
      for (int k8 = 0; k8 < 8; k8++) {
        const int prb = k8 * 4 + kl;
        uint2 a0[2], a1[2], bb[4];
#pragma unroll
        for (int t = 0; t < 2; t++) {
          int m = mbase + t * 16 + r;
          a0[t] = pxu[prb * PXS + m];
          a1[t] = pxu[prb * PXS + m + 8];
        }
#pragma unroll
        for (int u = 0; u < 4; u++) {
          int n = nbase + u * 8 + r;
          bb[u] = w2p[(prc + prb) * 128 + (n ^ (kl << 2))];
        }
#pragma unroll
        for (int t = 0; t < 2; t++)
#pragma unroll
          for (int u = 0; u < 4; u++)
            mma8(d2[t][u], a0[t].x, a1[t].x, a0[t].y, a1[t].y, bb[u].x, bb[u].y);
      }
    }

    // ================= epilogue: y = efeat + silu(D2+b2); LN =================
    float y[2][4][4];
    float s0[2], q0[2], s1[2], q1[2];
#pragma unroll
    for (int t = 0; t < 2; t++) { s0[t] = q0[t] = s1[t] = q1[t] = 0.f; }
#pragma unroll
    for (int t = 0; t < 2; t++) {
      int m = mbase + t * 16 + r;
#pragma unroll
      for (int u = 0; u < 4; u++) {
        int n = nbase + u * 8 + 2 * kl;
        float2 ef0 = *(const float2*)(efeat + (size_t)(e0 + m) * 128 + n);
        float2 ef1 = *(const float2*)(efeat + (size_t)(e0 + m + 8) * 128 + n);
        float v0 = ef0.x + silu_f(d2[t][u][0] + b2v[u][0]);
        float v1 = ef0.y + silu_f(d2[t][u][1] + b2v[u][1]);
        float v2 = ef1.x + silu_f(d2[t][u][2] + b2v[u][0]);
        float v3 = ef1.y + silu_f(d2[t][u][3] + b2v[u][1]);
        y[t][u][0] = v0; y[t][u][1] = v1; y[t][u][2] = v2; y[t][u][3] = v3;
        s0[t] += v0 + v1; q0[t] += v0 * v0 + v1 * v1;
        s1[t] += v2 + v3; q1[t] += v2 * v2 + v3 * v3;
      }
    }
#pragma unroll
    for (int t = 0; t < 2; t++) {
#pragma unroll
      for (int off = 1; off <= 2; off <<= 1) {
        s0[t] += __shfl_xor_sync(0xffffffffu, s0[t], off);
        q0[t] += __shfl_xor_sync(0xffffffffu, q0[t], off);
        s1[t] += __shfl_xor_sync(0xffffffffu, s1[t], off);
        q1[t] += __shfl_xor_sync(0xffffffffu, q1[t], off);
      }
    }
    __syncthreads();   // GEMM2 pxu reads complete
    float2* red = (float2*)pxu;   // [4 nj][128 m]
    if (kl == 0) {
#pragma unroll
      for (int t = 0; t < 2; t++) {
        int m = mbase + t * 16 + r;
        red[nj * 128 + m]     = make_float2(s0[t], q0[t]);
        red[nj * 128 + m + 8] = make_float2(s1[t], q1[t]);
      }
    }
    __syncthreads();
#pragma unroll
    for (int t = 0; t < 2; t++) {
      int m = mbase + t * 16 + r;
      float S0 = 0.f, Q0 = 0.f, S1 = 0.f, Q1 = 0.f;
#pragma unroll
      for (int qd = 0; qd < 4; qd++) {
        float2 v = red[qd * 128 + m];     S0 += v.x; Q0 += v.y;
        float2 w = red[qd * 128 + m + 8]; S1 += w.x; Q1 += w.y;
      }
      float mean0 = S0 * 0.0078125f;
      float var0  = Q0 * 0.0078125f - mean0 * mean0;
      float rs0   = rsqrtf(var0 + 1e-5f);
      float mean1 = S1 * 0.0078125f;
      float var1  = Q1 * 0.0078125f - mean1 * mean1;
      float rs1   = rsqrtf(var1 + 1e-5f);
#pragma unroll
      for (int u = 0; u < 4; u++) {
        int n = nbase + u * 8 + 2 * kl;
        float2 o0, o1;
        o0.x = (y[t][u][0] - mean0) * rs0 * gv[u][0] + btv[u][0];
        o0.y = (y[t][u][1] - mean0) * rs0 * gv[u][1] + btv[u][1];
        o1.x = (y[t][u][2] - mean1) * rs1 * gv[u][0] + btv[u][0];
        o1.y = (y[t][u][3] - mean1) * rs1 * gv[u][1] + btv[u][1];
        *(float2*)(out + (size_t)(e0 + m) * 128 + n)     = o0;
        *(float2*)(out + (size_t)(e0 + m + 8) * 128 + n) = o1;
      }
    }
    // next tile's first __syncthreads orders pxu/red reuse
  }
}

extern "C" void kernel_launch(void* const* d_in, const int* in_sizes, int n_in,
                              void* d_out, int out_size) {
  const float* nodes = (const float*)d_in[0];
  const float* efeat = (const float*)d_in[1];
  const int*   srcI  = (const int*)d_in[2];
  const int*   dstI  = (const int*)d_in[3];
  const float* W1    = (const float*)d_in[4];
  const float* b1    = (const float*)d_in[5];
  const float* W2    = (const float*)d_in[6];
  const float* b2    = (const float*)d_in[7];
  const float* gamma = (const float*)d_in[8];
  const float* beta  = (const float*)d_in[9];
  float* out = (float*)d_out;

  cudaFuncSetAttribute(edge_update_mma7,
                       cudaFuncAttributeMaxDynamicSharedMemorySize, SMEM_BYTES);
  int sms = 148;
  cudaDeviceGetAttribute(&sms, cudaDevAttrMultiProcessorCount, 0);
  if (sms < 1) sms = 148;

  edge_update_mma7<<<sms, THREADS, SMEM_BYTES>>>(
      nodes, efeat, srcI, dstI, W1, b1, W2, b2, gamma, beta, out);
}

// round 14
// speedup vs baseline: 1.2050x; 1.2050x over previous
#include <cuda_runtime.h>
#include <cstdint>

// EdgeUpdate via mma.sync.m16n8k8.tf32, 1024 threads / 32 warps (8/SMSP, occ 50%).
// Warp tile 16 edges x 32 outs (mi=warp>>2 in 0..7, nj=warp&3), 1x4 mma tiles.
// R7 memory formats; biases in smem; two-pass epilogue (no y array) for 64-reg fit.
#define THREADS 1024
#define NTILES  5000          // 640000 / 128
#define PXS     132           // uint2 pair-row stride AND float h1 stride (132%32=4)

// smem byte offsets
#define OW1 0                 // uint2 [128 pr][128 n] : 131072 B
#define OW2 131072            // uint2 [ 64 pr][128 n] :  65536 B
#define OX  196608            // pairs [32 pr][132]u2 / h1 [64 k][132]f / red : 33792 B
#define OB  230400            // b1,b2,gamma,beta : 2048 B
#define SMEM_BYTES 232448     // == opt-in cap

__device__ __forceinline__ unsigned tf32r(float x) {
  unsigned r; asm("cvt.rna.tf32.f32 %0, %1;" : "=r"(r) : "f"(x)); return r;
}
__device__ __forceinline__ float silu_f(float x) {
  return x * (1.0f / (1.0f + __expf(-x)));
}
__device__ __forceinline__ void mma8(float* d, unsigned a0, unsigned a1,
                                     unsigned a2, unsigned a3,
                                     unsigned b0, unsigned b1) {
  asm volatile("mma.sync.aligned.m16n8k8.row.col.f32.tf32.tf32.f32 "
    "{%0,%1,%2,%3}, {%4,%5,%6,%7}, {%8,%9}, {%0,%1,%2,%3};"
    : "+f"(d[0]), "+f"(d[1]), "+f"(d[2]), "+f"(d[3])
    : "r"(a0), "r"(a1), "r"(a2), "r"(a3), "r"(b0), "r"(b1));
}

__global__ void __launch_bounds__(THREADS, 1)
edge_update_mma8(const float* __restrict__ nodes,
                 const float* __restrict__ efeat,
                 const int*   __restrict__ srcI,
                 const int*   __restrict__ dstI,
                 const float* __restrict__ W1,
                 const float* __restrict__ b1,
                 const float* __restrict__ W2,
                 const float* __restrict__ b2,
                 const float* __restrict__ gamma,
                 const float* __restrict__ beta,
                 float* __restrict__ out)
{
  extern __shared__ char smem[];
  uint2* w1p = (uint2*)(smem + OW1);
  uint2* w2p = (uint2*)(smem + OW2);
  uint2* pxu = (uint2*)(smem + OX);          // [32 pr][PXS] pairs (GEMM1)
  unsigned* sxu = (unsigned*)(smem + OX);    // [64 k][PXS] unpacked h1 (GEMM2)
  const float2* sb1 = (const float2*)(smem + OB);
  const float2* sb2 = (const float2*)(smem + OB + 512);
  const float2* sgm = (const float2*)(smem + OB + 1024);
  const float2* sbt = (const float2*)(smem + OB + 1536);

  const int tid  = threadIdx.x;
  const int warp = tid >> 5, lane = tid & 31;
  const int kl = lane & 3, r = lane >> 2;
  const int mi = warp >> 2;            // edges [16*mi, 16*mi+16)
  const int nj = warp & 3;             // outs  [32*nj, 32*nj+32)
  const int mbase = mi * 16;
  const int nbase = nj * 32;

  // ---- stage weights as (k, k+4) tf32 pairs, swizzled n ^ ((pr&3)<<2) ----
  for (int i = tid; i < 16384; i += THREADS) {
    int pr = i >> 7, n = i & 127;
    int k0 = (pr >> 2) * 8 + (pr & 3);
    w1p[pr * 128 + (n ^ ((pr & 3) << 2))] =
        make_uint2(tf32r(W1[k0 * 128 + n]), tf32r(W1[(k0 + 4) * 128 + n]));
  }
  for (int i = tid; i < 8192; i += THREADS) {
    int pr = i >> 7, n = i & 127;
    int k0 = (pr >> 2) * 8 + (pr & 3);
    w2p[pr * 128 + (n ^ ((pr & 3) << 2))] =
        make_uint2(tf32r(W2[k0 * 128 + n]), tf32r(W2[(k0 + 4) * 128 + n]));
  }
  if (tid < 128) {
    ((float*)(smem + OB))[tid]        = b1[tid];
    ((float*)(smem + OB + 512))[tid]  = b2[tid];
    ((float*)(smem + OB + 1024))[tid] = gamma[tid];
    ((float*)(smem + OB + 1536))[tid] = beta[tid];
  }
  __syncthreads();

  for (int tile = blockIdx.x; tile < NTILES; tile += gridDim.x) {
    const int e0 = tile * 128;

    // ================= GEMM1: D1 = X[128,256] @ W1 =================
    float d1[4][4];
#pragma unroll
    for (int u = 0; u < 4; u++)
#pragma unroll
      for (int j = 0; j < 4; j++) d1[u][j] = 0.f;

#pragma unroll 1
    for (int c = 0; c < 4; c++) {
      __syncthreads();   // previous pxu use complete
      // gather 64-k chunk c -> pairs [32 pr][e] (raw fp32 bits)
      {
        const int e = tid & 127, g = tid >> 7;   // g: 0..7, one 8-k group each
        const float* base;
        if (c == 0)      base = nodes + (size_t)srcI[e0 + e] * 64;
        else if (c == 1) base = nodes + (size_t)dstI[e0 + e] * 64;
        else             base = efeat + (size_t)(e0 + e) * 128 + (c - 2) * 64;
        float4 v0 = ((const float4*)(base + g * 8))[0];
        float4 v1 = ((const float4*)(base + g * 8))[1];
        pxu[(4 * g + 0) * PXS + e] = make_uint2(__float_as_uint(v0.x), __float_as_uint(v1.x));
        pxu[(4 * g + 1) * PXS + e] = make_uint2(__float_as_uint(v0.y), __float_as_uint(v1.y));
        pxu[(4 * g + 2) * PXS + e] = make_uint2(__float_as_uint(v0.z), __float_as_uint(v1.z));
        pxu[(4 * g + 3) * PXS + e] = make_uint2(__float_as_uint(v0.w), __float_as_uint(v1.w));
      }
      __syncthreads();

      const int prc = c * 32;
#pragma unroll
      for (int k8 = 0; k8 < 8; k8++) {
        const int prb = k8 * 4 + kl;
        uint2 a0, a1, bb[4];
        {
          int m = mbase + r;
          a0 = pxu[prb * PXS + m];
          a1 = pxu[prb * PXS + m + 8];
        }
#pragma unroll
        for (int u = 0; u < 4; u++) {
          int n = nbase + u * 8 + r;
          bb[u] = w1p[(prc + prb) * 128 + (n ^ (kl << 2))];
        }
#pragma unroll
        for (int u = 0; u < 4; u++)
          mma8(d1[u], a0.x, a1.x, a0.y, a1.y, bb[u].x, bb[u].y);
      }
    }

    // ---- h1 = silu(D1 + b1), raw fp32 bits ----
    unsigned h1f[4][4];
#pragma unroll
    for (int u = 0; u < 4; u++) {
      float2 bv = sb1[(nbase + u * 8 + 2 * kl) >> 1];
      h1f[u][0] = __float_as_uint(silu_f(d1[u][0] + bv.x));
      h1f[u][1] = __float_as_uint(silu_f(d1[u][1] + bv.y));
      h1f[u][2] = __float_as_uint(silu_f(d1[u][2] + bv.x));
      h1f[u][3] = __float_as_uint(silu_f(d1[u][3] + bv.y));
    }

    // ================= GEMM2: D2 = H1[128,128] @ W2 =================
    float d2[4][4];
#pragma unroll
    for (int u = 0; u < 4; u++)
#pragma unroll
      for (int j = 0; j < 4; j++) d2[u][j] = 0.f;

#pragma unroll 1
    for (int c2 = 0; c2 < 2; c2++) {
      __syncthreads();   // prior pxu/sxu reads done
      if ((nj >> 1) == c2) {
        const int kloc0 = (nj & 1) * 32;
        const int m = mbase + r;
#pragma unroll
        for (int u = 0; u < 4; u++) {
          int kk = kloc0 + u * 8 + 2 * kl;
          sxu[kk * PXS + m]           = h1f[u][0];
          sxu[(kk + 1) * PXS + m]     = h1f[u][1];
          sxu[kk * PXS + m + 8]       = h1f[u][2];
          sxu[(kk + 1) * PXS + m + 8] = h1f[u][3];
        }
      }
      __syncthreads();

      const int prc = c2 * 32;
#pragma unroll
      for (int k8 = 0; k8 < 8; k8++) {
        const int kb = k8 * 8;
        unsigned a[4];
        uint2 bb[4];
        {
          int m = mbase + r;
          a[0] = sxu[(kb + kl) * PXS + m];
          a[1] = sxu[(kb + kl) * PXS + m + 8];
          a[2] = sxu[(kb + 4 + kl) * PXS + m];
          a[3] = sxu[(kb + 4 + kl) * PXS + m + 8];
        }
#pragma unroll
        for (int u = 0; u < 4; u++) {
          int n = nbase + u * 8 + r;
          bb[u] = w2p[(prc + k8 * 4 + kl) * 128 + (n ^ (kl << 2))];
        }
#pragma unroll
        for (int u = 0; u < 4; u++)
          mma8(d2[u], a[0], a[1], a[2], a[3], bb[u].x, bb[u].y);
      }
    }

    // ====== epilogue pass 1: s,q from y = efeat + silu(D2+b2) (y not kept) ======
    const int m = mbase + r;
    float s0 = 0.f, q0 = 0.f, s1 = 0.f, q1 = 0.f;
#pragma unroll
    for (int u = 0; u < 4; u++) {
      int n = nbase + u * 8 + 2 * kl;
      float2 bv = sb2[n >> 1];
      float2 ef0 = *(const float2*)(efeat + (size_t)(e0 + m) * 128 + n);
      float2 ef1 = *(const float2*)(efeat + (size_t)(e0 + m + 8) * 128 + n);
      float v0 = ef0.x + silu_f(d2[u][0] + bv.x);
      float v1 = ef0.y + silu_f(d2[u][1] + bv.y);
      float v2 = ef1.x + silu_f(d2[u][2] + bv.x);
      float v3 = ef1.y + silu_f(d2[u][3] + bv.y);
      s0 += v0 + v1; q0 += v0 * v0 + v1 * v1;
      s1 += v2 + v3; q1 += v2 * v2 + v3 * v3;
    }
#pragma unroll
    for (int off = 1; off <= 2; off <<= 1) {
      s0 += __shfl_xor_sync(0xffffffffu, s0, off);
      q0 += __shfl_xor_sync(0xffffffffu, q0, off);
      s1 += __shfl_xor_sync(0xffffffffu, s1, off);
      q1 += __shfl_xor_sync(0xffffffffu, q1, off);
    }
    __syncthreads();   // GEMM2 sxu reads complete
    float2* red = (float2*)sxu;   // [4 nj][128 m]
    if (kl == 0) {
      red[nj * 128 + m]     = make_float2(s0, q0);
      red[nj * 128 + m + 8] = make_float2(s1, q1);
    }
    __syncthreads();
    {
      float S0 = 0.f, Q0 = 0.f, S1 = 0.f, Q1 = 0.f;
#pragma unroll
      for (int qd = 0; qd < 4; qd++) {
        float2 v = red[qd * 128 + m];     S0 += v.x; Q0 += v.y;
        float2 w = red[qd * 128 + m + 8]; S1 += w.x; Q1 += w.y;
      }
      float mean0 = S0 * 0.0078125f;
      float rs0   = rsqrtf(Q0 * 0.0078125f - mean0 * mean0 + 1e-5f);
      float mean1 = S1 * 0.0078125f;
      float rs1   = rsqrtf(Q1 * 0.0078125f - mean1 * mean1 + 1e-5f);
      // ====== pass 2: recompute y, normalize, write ======
#pragma unroll
      for (int u = 0; u < 4; u++) {
        int n = nbase + u * 8 + 2 * kl;
        float2 bv = sb2[n >> 1];
        float2 gv = sgm[n >> 1];
        float2 tv = sbt[n >> 1];
        float2 ef0 = *(const float2*)(efeat + (size_t)(e0 + m) * 128 + n);
        float2 ef1 = *(const float2*)(efeat + (size_t)(e0 + m + 8) * 128 + n);
        float v0 = ef0.x + silu_f(d2[u][0] + bv.x);
        float v1 = ef0.y + silu_f(d2[u][1] + bv.y);
        float v2 = ef1.x + silu_f(d2[u][2] + bv.x);
        float v3 = ef1.y + silu_f(d2[u][3] + bv.y);
        float2 o0, o1;
        o0.x = (v0 - mean0) * rs0 * gv.x + tv.x;
        o0.y = (v1 - mean0) * rs0 * gv.y + tv.y;
        o1.x = (v2 - mean1) * rs1 * gv.x + tv.x;
        o1.y = (v3 - mean1) * rs1 * gv.y + tv.y;
        *(float2*)(out + (size_t)(e0 + m) * 128 + n)     = o0;
        *(float2*)(out + (size_t)(e0 + m + 8) * 128 + n) = o1;
      }
    }
    // next tile's first __syncthreads orders pxu/red reuse
  }
}

extern "C" void kernel_launch(void* const* d_in, const int* in_sizes, int n_in,
                              void* d_out, int out_size) {
  const float* nodes = (const float*)d_in[0];
  const float* efeat = (const float*)d_in[1];
  const int*   srcI  = (const int*)d_in[2];
  const int*   dstI  = (const int*)d_in[3];
  const float* W1    = (const float*)d_in[4];
  const float* b1    = (const float*)d_in[5];
  const float* W2    = (const float*)d_in[6];
  const float* b2    = (const float*)d_in[7];
  const float* gamma = (const float*)d_in[8];
  const float* beta  = (const float*)d_in[9];
  float* out = (float*)d_out;

  cudaFuncSetAttribute(edge_update_mma8,
                       cudaFuncAttributeMaxDynamicSharedMemorySize, SMEM_BYTES);
  int sms = 148;
  cudaDeviceGetAttribute(&sms, cudaDevAttrMultiProcessorCount, 0);
  if (sms < 1) sms = 148;

  edge_update_mma8<<<sms, THREADS, SMEM_BYTES>>>(
      nodes, efeat, srcI, dstI, W1, b1, W2, b2, gamma, beta, out);
}

// round 17
// speedup vs baseline: 1.4799x; 1.2282x over previous
#include <cuda_runtime.h>
#include <cstdint>

// EdgeUpdate split into two pipelined kernels via a __device__ h1 staging buffer.
// K1: h1 = silu([ns[src]|ns[dst]|ef] @ W1 + b1), written in (k,k+4) pair format.
// K2: out = LN(ef + silu(h1 @ W2 + b2)).
// R16 fix vs R15: k1_issue copies the FULL 64-float chunk per edge (4 cp.async/thread).
#define THREADS 512
#define NTILES  5000          // 640000 / 128
#define XST     68            // K1 x row stride (floats): conflict-free LDS.32
#define PXS     132           // K2 pair-row stride (uint2): conflict-free LDS.64

// K1 smem: W1 pairs 131072 | two x buffers 2x34816  -> 200704
#define K1_OW1  0
#define K1_OXA  131072
#define K1_OXB  (131072 + 34816)
#define K1_SMEM (131072 + 2 * 34816)
// K2 smem: W2 pairs 65536 | two h1 buffers 2x67584 | red 4096 -> 204800
#define K2_OW2  0
#define K2_OBA  65536
#define K2_OBB  (65536 + 67584)
#define K2_ORED (65536 + 2 * 67584)
#define K2_SMEM (65536 + 2 * 67584 + 4096)

__device__ __align__(16) float2 g_h1[(size_t)NTILES * 64 * 128];  // [tile][pr][e]

__device__ __forceinline__ unsigned smem_u32(const void* p) {
  unsigned a;
  asm("{ .reg .u64 t; cvta.to.shared.u64 t, %1; cvt.u32.u64 %0, t; }" : "=r"(a) : "l"(p));
  return a;
}
__device__ __forceinline__ unsigned tf32r(float x) {
  unsigned r; asm("cvt.rna.tf32.f32 %0, %1;" : "=r"(r) : "f"(x)); return r;
}
__device__ __forceinline__ float silu_f(float x) {
  return x * (1.0f / (1.0f + __expf(-x)));
}
__device__ __forceinline__ void mma8(float* d, unsigned a0, unsigned a1,
                                     unsigned a2, unsigned a3,
                                     unsigned b0, unsigned b1) {
  asm volatile("mma.sync.aligned.m16n8k8.row.col.f32.tf32.tf32.f32 "
    "{%0,%1,%2,%3}, {%4,%5,%6,%7}, {%8,%9}, {%0,%1,%2,%3};"
    : "+f"(d[0]), "+f"(d[1]), "+f"(d[2]), "+f"(d[3])
    : "r"(a0), "r"(a1), "r"(a2), "r"(a3), "r"(b0), "r"(b1));
}
__device__ __forceinline__ void cpa16(unsigned dst, const void* src) {
  asm volatile("cp.async.cg.shared.global [%0], [%1], 16;" :: "r"(dst), "l"(src));
}
#define CP_COMMIT() asm volatile("cp.async.commit_group;" ::: "memory")
#define CP_WAIT(n)  asm volatile("cp.async.wait_group %0;" :: "n"(n) : "memory")

// issue one 64-k chunk (128 edges x 64 floats = 32KB) via cp.async; 4 ops/thread
__device__ __forceinline__ void k1_issue(int tile, int c, unsigned dst, int tid,
                                         const float* nodes, const float* efeat,
                                         const int* srcI, const int* dstI) {
  int e = tid >> 2, j = tid & 3;          // edge 0..127, 16-float slice 0..3
  int eg = tile * 128 + e;
  const float* base;
  if (c == 0)      base = nodes + (size_t)srcI[eg] * 64;
  else if (c == 1) base = nodes + (size_t)dstI[eg] * 64;
  else             base = efeat + (size_t)eg * 128 + (c - 2) * 64;
  const float* src = base + j * 16;
  unsigned d0 = dst + (unsigned)(e * XST + j * 16) * 4;
#pragma unroll
  for (int i = 0; i < 4; i++) cpa16(d0 + i * 16, src + i * 4);
}

// ===================== Kernel 1: GEMM1 + silu -> g_h1 =====================
__global__ void __launch_bounds__(THREADS, 1)
k1_gemm1(const float* __restrict__ nodes, const float* __restrict__ efeat,
         const int* __restrict__ srcI, const int* __restrict__ dstI,
         const float* __restrict__ W1, const float* __restrict__ b1) {
  extern __shared__ char smem[];
  uint2* w1p = (uint2*)(smem + K1_OW1);
  const unsigned sb = smem_u32(smem);

  const int tid  = threadIdx.x;
  const int warp = tid >> 5, lane = tid & 31;
  const int kl = lane & 3, r = lane >> 2;
  const int mi = warp >> 2, nj = warp & 3;
  const int mbase = mi * 32, nbase = nj * 32;

  for (int i = tid; i < 16384; i += THREADS) {
    int pr = i >> 7, n = i & 127;
    int k0 = (pr >> 2) * 8 + (pr & 3);
    w1p[pr * 128 + (n ^ ((pr & 3) << 2))] =
        make_uint2(tf32r(W1[k0 * 128 + n]), tf32r(W1[(k0 + 4) * 128 + n]));
  }
  float b1v[4][2];
#pragma unroll
  for (int u = 0; u < 4; u++) {
    int n = nbase + u * 8 + 2 * kl;
    b1v[u][0] = b1[n]; b1v[u][1] = b1[n + 1];
  }
  __syncthreads();

  int cur = 0;
  if (blockIdx.x < NTILES) {
    k1_issue(blockIdx.x, 0, sb + K1_OXA, tid, nodes, efeat, srcI, dstI);
    CP_COMMIT();
  }
  for (int tile = blockIdx.x; tile < NTILES; tile += gridDim.x) {
    float d1[2][4][4];
#pragma unroll
    for (int t = 0; t < 2; t++)
#pragma unroll
      for (int u = 0; u < 4; u++)
#pragma unroll
        for (int j = 0; j < 4; j++) d1[t][u][j] = 0.f;

#pragma unroll 1
    for (int c = 0; c < 4; c++) {
      int nt = (c < 3) ? tile : tile + gridDim.x;
      int nc = (c < 3) ? c + 1 : 0;
      bool valid = nt < NTILES;
      if (valid) {
        k1_issue(nt, nc, sb + (cur ? K1_OXA : K1_OXB), tid, nodes, efeat, srcI, dstI);
        CP_COMMIT();
        CP_WAIT(1);
      } else {
        CP_WAIT(0);
      }
      __syncthreads();   // current buffer ready; previous reads done

      const float* xb = (const float*)(smem + (cur ? K1_OXB : K1_OXA));
      const int prc = c * 32;
#pragma unroll
      for (int k8 = 0; k8 < 8; k8++) {
        const int kb = k8 * 8;
        unsigned a[2][4];
        uint2 bb[4];
#pragma unroll
        for (int t = 0; t < 2; t++) {
          int m = mbase + t * 16 + r;
          a[t][0] = __float_as_uint(xb[m * XST + kb + kl]);
          a[t][1] = __float_as_uint(xb[(m + 8) * XST + kb + kl]);
          a[t][2] = __float_as_uint(xb[m * XST + kb + 4 + kl]);
          a[t][3] = __float_as_uint(xb[(m + 8) * XST + kb + 4 + kl]);
        }
#pragma unroll
        for (int u = 0; u < 4; u++) {
          int n = nbase + u * 8 + r;
          bb[u] = w1p[(prc + k8 * 4 + kl) * 128 + (n ^ (kl << 2))];
        }
#pragma unroll
        for (int t = 0; t < 2; t++)
#pragma unroll
          for (int u = 0; u < 4; u++)
            mma8(d1[t][u], a[t][0], a[t][1], a[t][2], a[t][3], bb[u].x, bb[u].y);
      }
      __syncthreads();   // buffer reads done before it becomes a cp.async target
      cur ^= 1;
    }

    // ---- h1 = silu(D1+b1) -> g_h1 in (k,k+4) pair format ----
    float2* gh = g_h1 + (size_t)tile * 64 * 128;
#pragma unroll
    for (int t = 0; t < 2; t++)
#pragma unroll
      for (int u = 0; u < 4; u++) {
        float h0 = silu_f(d1[t][u][0] + b1v[u][0]);
        float h1_ = silu_f(d1[t][u][1] + b1v[u][1]);
        float h2 = silu_f(d1[t][u][2] + b1v[u][0]);
        float h3 = silu_f(d1[t][u][3] + b1v[u][1]);
        float p0 = __shfl_xor_sync(0xffffffffu, h0, 2);
        float p1 = __shfl_xor_sync(0xffffffffu, h1_, 2);
        float p2 = __shfl_xor_sync(0xffffffffu, h2, 2);
        float p3 = __shfl_xor_sync(0xffffffffu, h3, 2);
        if (kl < 2) {
          int k = nbase + u * 8 + 2 * kl;        // k&7 in {0,2}
          int pra = (k >> 3) * 4 + (k & 3);
          int m = mbase + t * 16 + r;
          gh[pra * 128 + m]           = make_float2(h0, p0);
          gh[pra * 128 + m + 8]       = make_float2(h2, p2);
          gh[(pra + 1) * 128 + m]     = make_float2(h1_, p1);
          gh[(pra + 1) * 128 + m + 8] = make_float2(h3, p3);
        }
      }
  }
}

// ===================== Kernel 2: GEMM2 + residual + LN =====================
__global__ void __launch_bounds__(THREADS, 1)
k2_gemm2(const float* __restrict__ efeat, const float* __restrict__ W2,
         const float* __restrict__ b2, const float* __restrict__ gamma,
         const float* __restrict__ beta, float* __restrict__ out) {
  extern __shared__ char smem[];
  uint2* w2p = (uint2*)(smem + K2_OW2);
  const unsigned sb = smem_u32(smem);

  const int tid  = threadIdx.x;
  const int warp = tid >> 5, lane = tid & 31;
  const int kl = lane & 3, r = lane >> 2;
  const int mi = warp >> 2, nj = warp & 3;
  const int mbase = mi * 32, nbase = nj * 32;

  for (int i = tid; i < 8192; i += THREADS) {
    int pr = i >> 7, n = i & 127;
    int k0 = (pr >> 2) * 8 + (pr & 3);
    w2p[pr * 128 + (n ^ ((pr & 3) << 2))] =
        make_uint2(tf32r(W2[k0 * 128 + n]), tf32r(W2[(k0 + 4) * 128 + n]));
  }
  float b2v[4][2], gv[4][2], btv[4][2];
#pragma unroll
  for (int u = 0; u < 4; u++) {
    int n = nbase + u * 8 + 2 * kl;
    b2v[u][0] = b2[n];    b2v[u][1] = b2[n + 1];
    gv[u][0]  = gamma[n]; gv[u][1]  = gamma[n + 1];
    btv[u][0] = beta[n];  btv[u][1] = beta[n + 1];
  }
  __syncthreads();

  // dense tile prefetch: 64 rows x 128 float2 = 4096 x 16B; 8 per thread
  auto prefetch = [&](int tile, unsigned dstbase) {
    const char* src = (const char*)(g_h1 + (size_t)tile * 64 * 128);
#pragma unroll
    for (int i = 0; i < 8; i++) {
      int q = i * THREADS + tid;
      int row = q >> 6, col = q & 63;
      cpa16(dstbase + (unsigned)(row * (PXS * 8) + col * 16), src + q * 16);
    }
  };

  int cur = 0;
  if (blockIdx.x < NTILES) { prefetch(blockIdx.x, sb + K2_OBA); CP_COMMIT(); }
  float2* red = (float2*)(smem + K2_ORED);   // [4 nj][128 m]

  for (int tile = blockIdx.x; tile < NTILES; tile += gridDim.x) {
    const int e0 = tile * 128;
    int nt = tile + gridDim.x;
    bool valid = nt < NTILES;
    if (valid) {
      prefetch(nt, sb + (cur ? K2_OBA : K2_OBB));
      CP_COMMIT();
      CP_WAIT(1);
    } else {
      CP_WAIT(0);
    }
    __syncthreads();   // current buffer ready; prior red reads done

    const uint2* hb = (const uint2*)(smem + (cur ? K2_OBB : K2_OBA));
    float d2[2][4][4];
#pragma unroll
    for (int t = 0; t < 2; t++)
#pragma unroll
      for (int u = 0; u < 4; u++)
#pragma unroll
        for (int j = 0; j < 4; j++) d2[t][u][j] = 0.f;

#pragma unroll
    for (int k8 = 0; k8 < 16; k8++) {
      const int prb = k8 * 4 + kl;
      uint2 a0[2], a1[2], bb[4];
#pragma unroll
      for (int t = 0; t < 2; t++) {
        int m = mbase + t * 16 + r;
        a0[t] = hb[prb * PXS + m];
        a1[t] = hb[prb * PXS + m + 8];
      }
#pragma unroll
      for (int u = 0; u < 4; u++) {
        int n = nbase + u * 8 + r;
        bb[u] = w2p[prb * 128 + (n ^ (kl << 2))];
      }
#pragma unroll
      for (int t = 0; t < 2; t++)
#pragma unroll
        for (int u = 0; u < 4; u++)
          mma8(d2[t][u], a0[t].x, a1[t].x, a0[t].y, a1[t].y, bb[u].x, bb[u].y);
    }

    // ---- epilogue: y = efeat + silu(D2+b2); LN over 128 ----
    float y[2][4][4];
    float s0[2], q0[2], s1[2], q1[2];
#pragma unroll
    for (int t = 0; t < 2; t++) { s0[t] = q0[t] = s1[t] = q1[t] = 0.f; }
#pragma unroll
    for (int t = 0; t < 2; t++) {
      int m = mbase + t * 16 + r;
#pragma unroll
      for (int u = 0; u < 4; u++) {
        int n = nbase + u * 8 + 2 * kl;
        float2 ef0 = *(const float2*)(efeat + (size_t)(e0 + m) * 128 + n);
        float2 ef1 = *(const float2*)(efeat + (size_t)(e0 + m + 8) * 128 + n);
        float v0 = ef0.x + silu_f(d2[t][u][0] + b2v[u][0]);
        float v1 = ef0.y + silu_f(d2[t][u][1] + b2v[u][1]);
        float v2 = ef1.x + silu_f(d2[t][u][2] + b2v[u][0]);
        float v3 = ef1.y + silu_f(d2[t][u][3] + b2v[u][1]);
        y[t][u][0] = v0; y[t][u][1] = v1; y[t][u][2] = v2; y[t][u][3] = v3;
        s0[t] += v0 + v1; q0[t] += v0 * v0 + v1 * v1;
        s1[t] += v2 + v3; q1[t] += v2 * v2 + v3 * v3;
      }
    }
#pragma unroll
    for (int t = 0; t < 2; t++) {
#pragma unroll
      for (int off = 1; off <= 2; off <<= 1) {
        s0[t] += __shfl_xor_sync(0xffffffffu, s0[t], off);
        q0[t] += __shfl_xor_sync(0xffffffffu, q0[t], off);
        s1[t] += __shfl_xor_sync(0xffffffffu, s1[t], off);
        q1[t] += __shfl_xor_sync(0xffffffffu, q1[t], off);
      }
    }
    if (kl == 0) {
#pragma unroll
      for (int t = 0; t < 2; t++) {
        int m = mbase + t * 16 + r;
        red[nj * 128 + m]     = make_float2(s0[t], q0[t]);
        red[nj * 128 + m + 8] = make_float2(s1[t], q1[t]);
      }
    }
    __syncthreads();   // red visible; buffer reads done (safe cp.async target)
#pragma unroll
    for (int t = 0; t < 2; t++) {
      int m = mbase + t * 16 + r;
      float S0 = 0.f, Q0 = 0.f, S1 = 0.f, Q1 = 0.f;
#pragma unroll
      for (int qd = 0; qd < 4; qd++) {
        float2 v = red[qd * 128 + m];     S0 += v.x; Q0 += v.y;
        float2 w = red[qd * 128 + m + 8]; S1 += w.x; Q1 += w.y;
      }
      float mean0 = S0 * 0.0078125f;
      float rs0   = rsqrtf(Q0 * 0.0078125f - mean0 * mean0 + 1e-5f);
      float mean1 = S1 * 0.0078125f;
      float rs1   = rsqrtf(Q1 * 0.0078125f - mean1 * mean1 + 1e-5f);
#pragma unroll
      for (int u = 0; u < 4; u++) {
        int n = nbase + u * 8 + 2 * kl;
        float2 o0, o1;
        o0.x = (y[t][u][0] - mean0) * rs0 * gv[u][0] + btv[u][0];
        o0.y = (y[t][u][1] - mean0) * rs0 * gv[u][1] + btv[u][1];
        o1.x = (y[t][u][2] - mean1) * rs1 * gv[u][0] + btv[u][0];
        o1.y = (y[t][u][3] - mean1) * rs1 * gv[u][1] + btv[u][1];
        *(float2*)(out + (size_t)(e0 + m) * 128 + n)     = o0;
        *(float2*)(out + (size_t)(e0 + m + 8) * 128 + n) = o1;
      }
    }
    cur ^= 1;
    // next iteration's top __syncthreads orders red reuse
  }
}

extern "C" void kernel_launch(void* const* d_in, const int* in_sizes, int n_in,
                              void* d_out, int out_size) {
  const float* nodes = (const float*)d_in[0];
  const float* efeat = (const float*)d_in[1];
  const int*   srcI  = (const int*)d_in[2];
  const int*   dstI  = (const int*)d_in[3];
  const float* W1    = (const float*)d_in[4];
  const float* b1    = (const float*)d_in[5];
  const float* W2    = (const float*)d_in[6];
  const float* b2    = (const float*)d_in[7];
  const float* gamma = (const float*)d_in[8];
  const float* beta  = (const float*)d_in[9];
  float* out = (float*)d_out;

  cudaFuncSetAttribute(k1_gemm1, cudaFuncAttributeMaxDynamicSharedMemorySize, K1_SMEM);
  cudaFuncSetAttribute(k2_gemm2, cudaFuncAttributeMaxDynamicSharedMemorySize, K2_SMEM);
  int sms = 148;
  cudaDeviceGetAttribute(&sms, cudaDevAttrMultiProcessorCount, 0);
  if (sms < 1) sms = 148;

  k1_gemm1<<<sms, THREADS, K1_SMEM>>>(nodes, efeat, srcI, dstI, W1, b1);
  k2_gemm2<<<sms, THREADS, K2_SMEM>>>(efeat, W2, b2, gamma, beta, out);
}